// round 2
// baseline (speedup 1.0000x reference)
#include <cuda_runtime.h>
#include <math.h>

#define NH 16
#define HD 64
#define BB 2
#define SS 2048
#define DD 1024
#define ND (NH*HD)          // 1024
#define BHSD (BB*NH*SS*HD)  // 4,194,304 floats per tensor

// scratch: [0]=Q (transposed per-head [bh][d][s]), [1]=K (same), [2]=V ([bh][s][d])
__device__ float g_scr[3][BHSD];

// ---------------------------------------------------------------------------
// SGEMM: A[M=4096, K=1024] * W[K=1024, N=1024] -> per-head scratch
// BM=128, BN=128, BK=8, 256 threads, 8x8 per thread
// which: 0=Q, 1=K (both stored transposed [bh][d][s]), 2=V ([bh][s][d])
// ---------------------------------------------------------------------------
__global__ __launch_bounds__(256) void proj_kernel(
    const float* __restrict__ A, const float* __restrict__ W, int which)
{
    __shared__ float As[8][128];
    __shared__ float Bs[8][128];

    const int tid = threadIdx.x;
    const int m0 = blockIdx.y * 128;
    const int n0 = blockIdx.x * 128;

    const int arow = tid >> 1;          // 0..127
    const int acol = (tid & 1) * 4;     // 0 or 4
    const int brow = tid >> 5;          // 0..7
    const int bcol = (tid & 31) * 4;    // 0..124

    const int tx = tid & 15;
    const int ty = tid >> 4;

    const float* Ap = A + (size_t)(m0 + arow) * DD + acol;
    const float* Wp = W + (size_t)brow * ND + n0 + bcol;

    float acc[8][8];
    #pragma unroll
    for (int i = 0; i < 8; i++)
        #pragma unroll
        for (int j = 0; j < 8; j++) acc[i][j] = 0.f;

    for (int k0 = 0; k0 < DD; k0 += 8) {
        float4 av = *(const float4*)(Ap + k0);
        float4 bv = *(const float4*)(Wp + (size_t)k0 * ND);
        As[acol + 0][arow] = av.x;
        As[acol + 1][arow] = av.y;
        As[acol + 2][arow] = av.z;
        As[acol + 3][arow] = av.w;
        *(float4*)&Bs[brow][bcol] = bv;
        __syncthreads();

        #pragma unroll
        for (int kk = 0; kk < 8; kk++) {
            float a[8], b[8];
            *(float4*)&a[0] = *(const float4*)&As[kk][ty * 8];
            *(float4*)&a[4] = *(const float4*)&As[kk][ty * 8 + 4];
            *(float4*)&b[0] = *(const float4*)&Bs[kk][tx * 8];
            *(float4*)&b[4] = *(const float4*)&Bs[kk][tx * 8 + 4];
            #pragma unroll
            for (int i = 0; i < 8; i++)
                #pragma unroll
                for (int j = 0; j < 8; j++)
                    acc[i][j] += a[i] * b[j];
        }
        __syncthreads();
    }

    float* out = g_scr[which];
    const int row0 = m0 + ty * 8;       // global row (b*SS + s), tile never crosses b
    const int col0 = n0 + tx * 8;       // global col (h*64 + d), 8 cols within one head
    const int bidx = row0 / SS;
    const int s0   = row0 % SS;

    if (which < 2) {
        // transposed per-head layout: [(b*NH + h)*HD + d] * SS + s
        #pragma unroll
        for (int j = 0; j < 8; j++) {
            int col = col0 + j;
            int h = col >> 6, d = col & 63;
            float* dst = out + ((size_t)((bidx * NH + h) * HD + d)) * SS + s0;
            *(float4*)(dst)     = make_float4(acc[0][j], acc[1][j], acc[2][j], acc[3][j]);
            *(float4*)(dst + 4) = make_float4(acc[4][j], acc[5][j], acc[6][j], acc[7][j]);
        }
    } else {
        // head-major row layout: [(b*NH + h)*SS + s] * HD + d
        int h = col0 >> 6, d0 = col0 & 63;
        #pragma unroll
        for (int i = 0; i < 8; i++) {
            float* dst = out + ((size_t)(bidx * NH + h) * SS + s0 + i) * HD + d0;
            *(float4*)(dst)     = make_float4(acc[i][0], acc[i][1], acc[i][2], acc[i][3]);
            *(float4*)(dst + 4) = make_float4(acc[i][4], acc[i][5], acc[i][6], acc[i][7]);
        }
    }
}

// ---------------------------------------------------------------------------
// Flash attention: 64-query tile per block, 64-key tiles, online softmax.
// 256 threads; each thread owns 4 rows x 4 cols.
// Degenerate rows (all causal keys v_masked) require visiting future key
// tiles too (reference fp32 rounding makes masked-causal and masked-future
// scores exactly equal at -1e10) — gated behind a block-wide flag.
// ---------------------------------------------------------------------------
__global__ __launch_bounds__(256) void attn_kernel(
    const int* __restrict__ v_mask, const int* __restrict__ q_mask,
    float* __restrict__ out)
{
    extern __shared__ float sm[];
    float* Qt = sm;                 // [64][64]  Qt[d][q]
    float* Kt = Qt + 64 * 64;       // [64][64]  Kt[d][c]
    float* Vs = Kt + 64 * 64;       // [64][64]  Vs[k][d]
    float* Ps = Vs + 64 * 64;       // [64][68]  probabilities (padded stride)
    float* kb = Ps + 64 * 68;       // [64]      key bias

    __shared__ int s_deg;

    const int tid = threadIdx.x;
    const int tx = tid & 15;
    const int ty = tid >> 4;
    const int qt = blockIdx.x;
    const int bh = blockIdx.y;
    const int b  = bh >> 4;         // / NH
    const int h  = bh & 15;
    const int q0 = qt * 64;
    const int NT = SS / 64;

    const float* Qg = g_scr[0] + (size_t)bh * HD * SS;
    const float* Kg = g_scr[1] + (size_t)bh * HD * SS;
    const float* Vg = g_scr[2] + (size_t)bh * SS * HD;

    // load Q tile: Qt[d][q] <- Qg[d*SS + q0 + q]
    #pragma unroll
    for (int it = 0; it < 4; it++) {
        int e  = tid + it * 256;    // float4 index 0..1023
        int d  = e >> 4;
        int c4 = (e & 15) << 2;
        *(float4*)&Qt[d * 64 + c4] = *(const float4*)(Qg + (size_t)d * SS + q0 + c4);
    }

    const int r0 = ty * 4;
    const int c0 = tx * 4;
    const float NEG_INF = __int_as_float(0xff800000);

    float m[4], l[4], acc[4][4];
    #pragma unroll
    for (int i = 0; i < 4; i++) {
        m[i] = NEG_INF; l[i] = 0.f;
        #pragma unroll
        for (int j = 0; j < 4; j++) acc[i][j] = 0.f;
    }

    int deg_flag = 0;   // uniform across block once set at kt == qt

    for (int kt = 0; kt < NT; kt++) {
        if (kt > qt && !deg_flag) break;
        const int k0 = kt * 64;

        #pragma unroll
        for (int it = 0; it < 4; it++) {
            int e  = tid + it * 256;
            int rr = e >> 4;
            int c4 = (e & 15) << 2;
            *(float4*)&Kt[rr * 64 + c4] = *(const float4*)(Kg + (size_t)rr * SS + k0 + c4);
            *(float4*)&Vs[rr * 64 + c4] = *(const float4*)(Vg + (size_t)(k0 + rr) * HD + c4);
        }
        if (tid < 64) {
            int vm = v_mask[b * SS + k0 + tid];
            kb[tid] = vm ? 0.f : -1e10f;
        }
        __syncthreads();

        // scores: S[r][c] = sum_d Qt[d][r] * Kt[d][c]
        float sc[4][4];
        #pragma unroll
        for (int i = 0; i < 4; i++)
            #pragma unroll
            for (int j = 0; j < 4; j++) sc[i][j] = 0.f;

        #pragma unroll 4
        for (int kk = 0; kk < 64; kk++) {
            float a[4], bq[4];
            *(float4*)a  = *(const float4*)&Qt[kk * 64 + r0];
            *(float4*)bq = *(const float4*)&Kt[kk * 64 + c0];
            #pragma unroll
            for (int i = 0; i < 4; i++)
                #pragma unroll
                for (int j = 0; j < 4; j++)
                    sc[i][j] += a[i] * bq[j];
        }

        // scale + key-padding bias + causal (exact reference op order)
        #pragma unroll
        for (int i = 0; i < 4; i++) {
            int qg = q0 + r0 + i;
            #pragma unroll
            for (int j = 0; j < 4; j++) {
                float s = sc[i][j] * 0.125f + kb[c0 + j];
                if (k0 + c0 + j > qg) s -= 1e10f;
                sc[i][j] = s;
            }
        }

        // online softmax, per-row reduction across the 16 lanes of this half-warp
        #pragma unroll
        for (int i = 0; i < 4; i++) {
            float tmax = fmaxf(fmaxf(sc[i][0], sc[i][1]), fmaxf(sc[i][2], sc[i][3]));
            #pragma unroll
            for (int o = 1; o < 16; o <<= 1)
                tmax = fmaxf(tmax, __shfl_xor_sync(0xffffffffu, tmax, o));
            float nm = fmaxf(m[i], tmax);

            float p0 = __expf(sc[i][0] - nm);
            float p1 = __expf(sc[i][1] - nm);
            float p2 = __expf(sc[i][2] - nm);
            float p3 = __expf(sc[i][3] - nm);
            float rs = (p0 + p1) + (p2 + p3);
            #pragma unroll
            for (int o = 1; o < 16; o <<= 1)
                rs += __shfl_xor_sync(0xffffffffu, rs, o);

            float alpha = __expf(m[i] - nm);
            l[i] = l[i] * alpha + rs;
            m[i] = nm;
            #pragma unroll
            for (int j = 0; j < 4; j++) acc[i][j] *= alpha;

            *(float4*)&Ps[(r0 + i) * 68 + c0] = make_float4(p0, p1, p2, p3);
        }
        __syncthreads();

        // O += P @ V
        #pragma unroll 2
        for (int kk = 0; kk < 64; kk++) {
            float vv[4];
            *(float4*)vv = *(const float4*)&Vs[kk * 64 + c0];
            #pragma unroll
            for (int i = 0; i < 4; i++) {
                float p = Ps[(r0 + i) * 68 + kk];
                #pragma unroll
                for (int j = 0; j < 4; j++)
                    acc[i][j] += p * vv[j];
            }
        }
        __syncthreads();

        // after the diagonal tile, decide if any row is degenerate
        // (all causal keys masked -> m == -1e10; normal rows have m = O(1))
        if (kt == qt) {
            if (tid == 0) s_deg = 0;
            __syncthreads();
            bool deg = (m[0] < -5e9f) | (m[1] < -5e9f) |
                       (m[2] < -5e9f) | (m[3] < -5e9f);
            if (deg) s_deg = 1;
            __syncthreads();
            deg_flag = s_deg;
        }
    }

    // epilogue: normalize, apply q_mask, write [b][s][h*64 + d]
    #pragma unroll
    for (int i = 0; i < 4; i++) {
        int qg = q0 + r0 + i;
        float qm = (float)q_mask[b * SS + qg];
        float f = (1.f / l[i]) * qm;
        float4 o = make_float4(acc[i][0] * f, acc[i][1] * f,
                               acc[i][2] * f, acc[i][3] * f);
        *(float4*)(out + ((size_t)b * SS + qg) * ND + h * HD + c0) = o;
    }
}

// ---------------------------------------------------------------------------
extern "C" void kernel_launch(void* const* d_in, const int* in_sizes, int n_in,
                              void* d_out, int out_size)
{
    const float* q  = (const float*)d_in[0];
    const float* k  = (const float*)d_in[1];
    const float* v  = (const float*)d_in[2];
    const int* vmask = (const int*)d_in[3];
    const int* qmask = (const int*)d_in[4];
    const float* Wq = (const float*)d_in[5];
    const float* Wk = (const float*)d_in[6];
    const float* Wv = (const float*)d_in[7];
    float* out = (float*)d_out;

    const int smem_attn = (64 * 64 * 3 + 64 * 68 + 64) * sizeof(float); // 66816 B
    cudaFuncSetAttribute(attn_kernel, cudaFuncAttributeMaxDynamicSharedMemorySize, smem_attn);

    dim3 gp(ND / 128, (BB * SS) / 128);   // (8, 32)
    proj_kernel<<<gp, 256>>>(q, Wq, 0);
    proj_kernel<<<gp, 256>>>(k, Wk, 1);
    proj_kernel<<<gp, 256>>>(v, Wv, 2);

    dim3 ga(SS / 64, BB * NH);            // (32, 32)
    attn_kernel<<<ga, 256, smem_attn>>>(vmask, qmask, out);
}

// round 3
// speedup vs baseline: 1.3915x; 1.3915x over previous
#include <cuda_runtime.h>

#define NH 16
#define HD 64
#define BB 2
#define SS 2048
#define DD 1024
#define ND (NH*HD)          // 1024
#define BHSD (BB*NH*SS*HD)  // 4,194,304 elems per tensor

// scratch Q,K,V as TF32 bit patterns, layout [bh][s][d]
__device__ unsigned g_scr[3][BHSD];

__device__ __forceinline__ unsigned f2tf(float x) {
    unsigned r; asm("cvt.rna.tf32.f32 %0, %1;" : "=r"(r) : "f"(x)); return r;
}

__device__ __forceinline__ void mma8(float* c, const unsigned* a, const unsigned* b) {
    asm volatile(
        "mma.sync.aligned.m16n8k8.row.col.f32.tf32.tf32.f32 "
        "{%0,%1,%2,%3}, {%4,%5,%6,%7}, {%8,%9}, {%0,%1,%2,%3};\n"
        : "+f"(c[0]), "+f"(c[1]), "+f"(c[2]), "+f"(c[3])
        : "r"(a[0]), "r"(a[1]), "r"(a[2]), "r"(a[3]), "r"(b[0]), "r"(b[1]));
}

__device__ __forceinline__ void split_tf(float x, unsigned& h, unsigned& l) {
    unsigned hb = f2tf(x);
    float r = x - __uint_as_float(hb);
    h = hb; l = f2tf(r);
}

// ---------------------------------------------------------------------------
// Projections: A[4096,1024] @ W[1024,1024] -> g_scr[z] as TF32, [bh][s][d].
// 3xTF32 (hi/lo split) for fp32-class accuracy. BM=128,BN=128,BK=16, 8 warps.
// blockIdx.z selects which projection (0=Q,1=K,2=V).
// ---------------------------------------------------------------------------
__global__ __launch_bounds__(256) void proj_kernel(
    const float* __restrict__ q, const float* __restrict__ k, const float* __restrict__ v,
    const float* __restrict__ Wq, const float* __restrict__ Wk, const float* __restrict__ Wv)
{
    __shared__ unsigned AsH[128][20], AsL[128][20];
    __shared__ unsigned WsH[16][132], WsL[16][132];

    const int which = blockIdx.z;
    const float* A = which == 0 ? q : (which == 1 ? k : v);
    const float* W = which == 0 ? Wq : (which == 1 ? Wk : Wv);

    const int tid = threadIdx.x;
    const int lane = tid & 31;
    const int w = tid >> 5;
    const int gid = lane >> 2, tig = lane & 3;
    const int wm = w >> 2, wn = w & 3;          // 2x4 warp grid
    const int m0 = blockIdx.y * 128, n0 = blockIdx.x * 128;

    const int am = tid >> 1, ak = (tid & 1) * 8;
    const int wr = tid >> 4, wc = (tid & 15) * 8;

    const float* Ap = A + (size_t)(m0 + am) * DD + ak;
    const float* Wp = W + (size_t)wr * ND + n0 + wc;

    float C[4][4][4];
    #pragma unroll
    for (int i = 0; i < 4; i++)
        #pragma unroll
        for (int j = 0; j < 4; j++)
            #pragma unroll
            for (int e = 0; e < 4; e++) C[i][j][e] = 0.f;

    for (int k0 = 0; k0 < DD; k0 += 16) {
        float4 a0 = *(const float4*)(Ap + k0);
        float4 a1 = *(const float4*)(Ap + k0 + 4);
        float4 w0 = *(const float4*)(Wp + (size_t)k0 * ND);
        float4 w1 = *(const float4*)(Wp + (size_t)k0 * ND + 4);
        __syncthreads();
        {
            unsigned h0,l0,h1,l1,h2,l2,h3,l3;
            split_tf(a0.x,h0,l0); split_tf(a0.y,h1,l1); split_tf(a0.z,h2,l2); split_tf(a0.w,h3,l3);
            *(uint4*)&AsH[am][ak]   = make_uint4(h0,h1,h2,h3);
            *(uint4*)&AsL[am][ak]   = make_uint4(l0,l1,l2,l3);
            split_tf(a1.x,h0,l0); split_tf(a1.y,h1,l1); split_tf(a1.z,h2,l2); split_tf(a1.w,h3,l3);
            *(uint4*)&AsH[am][ak+4] = make_uint4(h0,h1,h2,h3);
            *(uint4*)&AsL[am][ak+4] = make_uint4(l0,l1,l2,l3);
            split_tf(w0.x,h0,l0); split_tf(w0.y,h1,l1); split_tf(w0.z,h2,l2); split_tf(w0.w,h3,l3);
            *(uint4*)&WsH[wr][wc]   = make_uint4(h0,h1,h2,h3);
            *(uint4*)&WsL[wr][wc]   = make_uint4(l0,l1,l2,l3);
            split_tf(w1.x,h0,l0); split_tf(w1.y,h1,l1); split_tf(w1.z,h2,l2); split_tf(w1.w,h3,l3);
            *(uint4*)&WsH[wr][wc+4] = make_uint4(h0,h1,h2,h3);
            *(uint4*)&WsL[wr][wc+4] = make_uint4(l0,l1,l2,l3);
        }
        __syncthreads();

        #pragma unroll
        for (int ks = 0; ks < 2; ks++) {
            const int kk = ks * 8;
            unsigned ah[4][4], al[4][4], bh[4][2], bl[4][2];
            #pragma unroll
            for (int mf = 0; mf < 4; mf++) {
                int r = wm * 64 + mf * 16 + gid;
                ah[mf][0] = AsH[r][kk+tig];     al[mf][0] = AsL[r][kk+tig];
                ah[mf][1] = AsH[r+8][kk+tig];   al[mf][1] = AsL[r+8][kk+tig];
                ah[mf][2] = AsH[r][kk+tig+4];   al[mf][2] = AsL[r][kk+tig+4];
                ah[mf][3] = AsH[r+8][kk+tig+4]; al[mf][3] = AsL[r+8][kk+tig+4];
            }
            #pragma unroll
            for (int nf = 0; nf < 4; nf++) {
                int c = wn * 32 + nf * 8 + gid;
                bh[nf][0] = WsH[kk+tig][c];   bl[nf][0] = WsL[kk+tig][c];
                bh[nf][1] = WsH[kk+tig+4][c]; bl[nf][1] = WsL[kk+tig+4][c];
            }
            #pragma unroll
            for (int mf = 0; mf < 4; mf++)
                #pragma unroll
                for (int nf = 0; nf < 4; nf++) {
                    mma8(C[mf][nf], ah[mf], bl[nf]);
                    mma8(C[mf][nf], al[mf], bh[nf]);
                    mma8(C[mf][nf], ah[mf], bh[nf]);
                }
        }
    }

    // epilogue: convert to TF32 bits, store to [bh][s][d]
    unsigned* out = g_scr[which];
    #pragma unroll
    for (int mf = 0; mf < 4; mf++) {
        int R = m0 + wm * 64 + mf * 16 + gid;
        #pragma unroll
        for (int half = 0; half < 2; half++) {
            int Rr = R + half * 8;
            int bb = Rr >> 11;
            int s  = Rr & 2047;
            #pragma unroll
            for (int nf = 0; nf < 4; nf++) {
                int Cc = n0 + wn * 32 + nf * 8 + tig * 2;
                int hh = Cc >> 6, dd = Cc & 63;
                size_t addr = ((size_t)(bb * NH + hh) * SS + s) * HD + dd;
                uint2 vv;
                vv.x = f2tf(C[mf][nf][half * 2 + 0]);
                vv.y = f2tf(C[mf][nf][half * 2 + 1]);
                *(uint2*)&out[addr] = vv;
            }
        }
    }
}

// ---------------------------------------------------------------------------
// Flash attention, TF32 mma. 64-query tile, 4 warps x 16 rows. 64-key tiles.
// Degenerate fully-masked rows continue into future tiles (reference fp32
// rounding makes all masked scores exactly -1e10 / -2e10).
// ---------------------------------------------------------------------------
__global__ __launch_bounds__(128) void attn_kernel(
    const int* __restrict__ v_mask, const int* __restrict__ q_mask,
    float* __restrict__ out)
{
    extern __shared__ unsigned smu[];
    unsigned* Qs = smu;                 // [64][68]
    unsigned* Ks = Qs + 64 * 68;
    unsigned* Vs = Ks + 64 * 68;
    unsigned* Ps = Vs + 64 * 68;
    float* kb   = (float*)(Ps + 64 * 68);   // [64]
    int* s_deg  = (int*)(kb + 64);

    const int tid = threadIdx.x;
    const int lane = tid & 31;
    const int w = tid >> 5;
    const int gid = lane >> 2, tig = lane & 3;
    const int qt = blockIdx.x, bh = blockIdx.y;
    const int b = bh >> 4, h = bh & 15;
    const int q0 = qt * 64;

    const unsigned* Qg = g_scr[0] + (size_t)bh * SS * HD;
    const unsigned* Kg = g_scr[1] + (size_t)bh * SS * HD;
    const unsigned* Vg = g_scr[2] + (size_t)bh * SS * HD;

    const int lr = tid >> 1, lc = (tid & 1) * 32;

    // load Q tile (already TF32 bits)
    {
        const unsigned* src = Qg + (size_t)(q0 + lr) * HD + lc;
        #pragma unroll
        for (int j = 0; j < 8; j++)
            *(uint4*)&Qs[lr * 68 + lc + j * 4] = *(const uint4*)(src + j * 4);
    }

    const float NEG_INF = __int_as_float(0xff800000);
    float m[2] = {NEG_INF, NEG_INF}, l[2] = {0.f, 0.f};
    float acc[8][4];
    #pragma unroll
    for (int nf = 0; nf < 8; nf++)
        #pragma unroll
        for (int e = 0; e < 4; e++) acc[nf][e] = 0.f;

    int deg = 0;
    const int rq = w * 16 + gid;

    for (int kt = 0; kt < SS / 64; kt++) {
        if (kt > qt && !deg) break;
        const int k0 = kt * 64;
        __syncthreads();
        {
            const unsigned* ks = Kg + (size_t)(k0 + lr) * HD + lc;
            const unsigned* vs = Vg + (size_t)(k0 + lr) * HD + lc;
            #pragma unroll
            for (int j = 0; j < 8; j++) {
                *(uint4*)&Ks[lr * 68 + lc + j * 4] = *(const uint4*)(ks + j * 4);
                *(uint4*)&Vs[lr * 68 + lc + j * 4] = *(const uint4*)(vs + j * 4);
            }
            if (tid < 64) kb[tid] = v_mask[b * SS + k0 + tid] ? 0.f : -1e10f;
        }
        __syncthreads();

        // S = Q @ K^T (over d=64)
        float sc[8][4];
        #pragma unroll
        for (int nf = 0; nf < 8; nf++)
            #pragma unroll
            for (int e = 0; e < 4; e++) sc[nf][e] = 0.f;

        #pragma unroll
        for (int kk = 0; kk < 8; kk++) {
            unsigned a[4];
            a[0] = Qs[rq * 68 + kk * 8 + tig];
            a[1] = Qs[(rq + 8) * 68 + kk * 8 + tig];
            a[2] = Qs[rq * 68 + kk * 8 + tig + 4];
            a[3] = Qs[(rq + 8) * 68 + kk * 8 + tig + 4];
            #pragma unroll
            for (int nf = 0; nf < 8; nf++) {
                unsigned bf[2];
                bf[0] = Ks[(nf * 8 + gid) * 68 + kk * 8 + tig];
                bf[1] = Ks[(nf * 8 + gid) * 68 + kk * 8 + tig + 4];
                mma8(sc[nf], a, bf);
            }
        }

        // mask + online softmax (2 rows per thread; quad lanes share a row)
        #pragma unroll
        for (int i = 0; i < 2; i++) {
            int qg = q0 + rq + 8 * i;
            float mx = NEG_INF;
            #pragma unroll
            for (int nf = 0; nf < 8; nf++)
                #pragma unroll
                for (int jj = 0; jj < 2; jj++) {
                    int kc = nf * 8 + tig * 2 + jj;
                    float s = sc[nf][2 * i + jj] * 0.125f + kb[kc];
                    if (k0 + kc > qg) s -= 1e10f;
                    sc[nf][2 * i + jj] = s;
                    mx = fmaxf(mx, s);
                }
            mx = fmaxf(mx, __shfl_xor_sync(0xffffffffu, mx, 1));
            mx = fmaxf(mx, __shfl_xor_sync(0xffffffffu, mx, 2));
            float nm = fmaxf(m[i], mx);
            float rs = 0.f;
            #pragma unroll
            for (int nf = 0; nf < 8; nf++)
                #pragma unroll
                for (int jj = 0; jj < 2; jj++) {
                    float p = __expf(sc[nf][2 * i + jj] - nm);
                    sc[nf][2 * i + jj] = p;
                    rs += p;
                }
            rs += __shfl_xor_sync(0xffffffffu, rs, 1);
            rs += __shfl_xor_sync(0xffffffffu, rs, 2);
            float alpha = __expf(m[i] - nm);
            l[i] = l[i] * alpha + rs;
            m[i] = nm;
            #pragma unroll
            for (int nf = 0; nf < 8; nf++) {
                acc[nf][2 * i + 0] *= alpha;
                acc[nf][2 * i + 1] *= alpha;
                Ps[(rq + 8 * i) * 68 + nf * 8 + tig * 2 + 0] = f2tf(sc[nf][2 * i + 0]);
                Ps[(rq + 8 * i) * 68 + nf * 8 + tig * 2 + 1] = f2tf(sc[nf][2 * i + 1]);
            }
        }
        __syncwarp();

        // O += P @ V (over 64 keys)
        #pragma unroll
        for (int kk = 0; kk < 8; kk++) {
            unsigned a[4];
            a[0] = Ps[rq * 68 + kk * 8 + tig];
            a[1] = Ps[(rq + 8) * 68 + kk * 8 + tig];
            a[2] = Ps[rq * 68 + kk * 8 + tig + 4];
            a[3] = Ps[(rq + 8) * 68 + kk * 8 + tig + 4];
            #pragma unroll
            for (int nf = 0; nf < 8; nf++) {
                unsigned bf[2];
                bf[0] = Vs[(kk * 8 + tig) * 68 + nf * 8 + gid];
                bf[1] = Vs[(kk * 8 + tig + 4) * 68 + nf * 8 + gid];
                mma8(acc[nf], a, bf);
            }
        }

        if (kt == qt) {
            if (tid == 0) *s_deg = 0;
            __syncthreads();
            if (m[0] < -5e9f || m[1] < -5e9f) *s_deg = 1;
            __syncthreads();
            deg = *s_deg;
        }
    }

    // epilogue
    #pragma unroll
    for (int i = 0; i < 2; i++) {
        int qg = q0 + rq + 8 * i;
        float qm = (float)q_mask[b * SS + qg];
        float f = qm / l[i];
        #pragma unroll
        for (int nf = 0; nf < 8; nf++) {
            float2 o = make_float2(acc[nf][2 * i + 0] * f, acc[nf][2 * i + 1] * f);
            *(float2*)(out + ((size_t)b * SS + qg) * ND + h * HD + nf * 8 + tig * 2) = o;
        }
    }
}

// ---------------------------------------------------------------------------
extern "C" void kernel_launch(void* const* d_in, const int* in_sizes, int n_in,
                              void* d_out, int out_size)
{
    const float* q  = (const float*)d_in[0];
    const float* k  = (const float*)d_in[1];
    const float* v  = (const float*)d_in[2];
    const int* vmask = (const int*)d_in[3];
    const int* qmask = (const int*)d_in[4];
    const float* Wq = (const float*)d_in[5];
    const float* Wk = (const float*)d_in[6];
    const float* Wv = (const float*)d_in[7];
    float* out = (float*)d_out;

    const int smem_attn = (4 * 64 * 68) * 4 + 64 * 4 + 16;   // ~69.9 KB
    cudaFuncSetAttribute(attn_kernel, cudaFuncAttributeMaxDynamicSharedMemorySize, smem_attn);

    dim3 gp(ND / 128, (BB * SS) / 128, 3);   // (8, 32, 3)
    proj_kernel<<<gp, 256>>>(q, k, v, Wq, Wk, Wv);

    dim3 ga(SS / 64, BB * NH);               // (32, 32)
    attn_kernel<<<ga, 128, smem_attn>>>(vmask, qmask, out);
}